// round 14
// baseline (speedup 1.0000x reference)
#include <cuda_runtime.h>
#include <cstdint>

// PolynomialFeatures: out[b] = concat(x[b], x[b, idx_a] * x[b, idx_b])
// x: [B, 256] fp32, out: [B, 256+32640] fp32.
//
// v10: warp-uniform i-major sweep.
//  - Each WARP owns one combination run i (pairs (i, i+1..255)): all lanes
//    share i -> no divergence; a = x[i] (4 rows packed float4) loaded ONCE
//    per run into registers.
//  - Lanes sweep the run's output quads: per iter 4 b-LDS.128 : 4 STG.128
//    (1:1 smem:store bytes vs 2:1 in v4/v8), no sqrt/boundary fixups.
//  - Run head/tail (output-quad alignment) handled by <=3-elem predicated
//    scalar stores per run.
//  - THREADS=192, __launch_bounds__(192,7): one wave (148*7=1036 >= 1024
//    blocks) with a 48-reg budget that fits the ~44-reg body (no spills).

#define ROWS_PER_BLOCK 4
#define F_FEAT 256
#define THREADS 192
#define NWARPS 6
#define NPAIRS_EXPECTED 32640   // 256*255/2

__device__ __forceinline__ int pbase(int i) {
    // start of run i: 255*i - i*(i-1)/2
    return i * 255 - ((i * (i - 1)) >> 1);
}
// interleave: consecutive-by-4 features land in adjacent float4 slots
// (lane-stride-16B accesses => conflict-free)
__device__ __forceinline__ int il(int j) {
    return (j >> 2) + (j & 3) * 64;
}

__global__ __launch_bounds__(THREADS, 7)
void poly_features_v10(const float* __restrict__ x,
                       float*       __restrict__ out,
                       int B)
{
    __shared__ float4 sx4[F_FEAT];   // sx4[il(j)] = {row0..row3} of feature j

    const int row0 = blockIdx.x * ROWS_PER_BLOCK;
    const int t    = threadIdx.x;
    const int wid  = t >> 5;
    const int lane = t & 31;
    const size_t ostride = (size_t)(F_FEAT + NPAIRS_EXPECTED);
    const int rows_here = min(ROWS_PER_BLOCK, B - row0);
    const bool full = (rows_here == ROWS_PER_BLOCK);

    // Stage feature f for the 4 rows; copy x -> out[:, :F].
    for (int f = t; f < F_FEAT; f += THREADS) {
        float v0 = 0.f, v1 = 0.f, v2 = 0.f, v3 = 0.f;
        v0 = x[(size_t)(row0 + 0) * F_FEAT + f];
        out[(size_t)(row0 + 0) * ostride + f] = v0;
        if (rows_here > 1) { v1 = x[(size_t)(row0 + 1) * F_FEAT + f];
                             out[(size_t)(row0 + 1) * ostride + f] = v1; }
        if (rows_here > 2) { v2 = x[(size_t)(row0 + 2) * F_FEAT + f];
                             out[(size_t)(row0 + 2) * ostride + f] = v2; }
        if (rows_here > 3) { v3 = x[(size_t)(row0 + 3) * F_FEAT + f];
                             out[(size_t)(row0 + 3) * ostride + f] = v3; }
        sx4[il(f)] = make_float4(v0, v1, v2, v3);
    }
    __syncthreads();

    float* ob0 = out + (size_t)(row0 + 0) * ostride + F_FEAT;
    float* ob1 = out + (size_t)(row0 + 1) * ostride + F_FEAT;
    float* ob2 = out + (size_t)(row0 + 2) * ostride + F_FEAT;
    float* ob3 = out + (size_t)(row0 + 3) * ostride + F_FEAT;

    // Each warp sweeps runs i = wid, wid+6, ... (warp-uniform i).
    for (int i = wid; i < 255; i += NWARPS) {
        const int s   = pbase(i);        // run start position
        const int len = 255 - i;         // run length
        const int e   = s + len;         // run end (exclusive)
        const float4 a = sx4[il(i)];     // broadcast load, lives in registers

        // Head: unaligned start, <=3 elements.
        const int head_n = min(len, (4 - (s & 3)) & 3);
        if (lane < head_n) {
            const int p = s + lane;
            const int j = i + 1 + lane;
            const float4 b = sx4[il(j)];
            ob0[p] = a.x * b.x;
            if (rows_here > 1) ob1[p] = a.y * b.y;
            if (rows_here > 2) ob2[p] = a.z * b.z;
            if (rows_here > 3) ob3[p] = a.w * b.w;
        }

        // Aligned quads.
        const int qs = (s + head_n) >> 2;
        const int qe = e >> 2;
        for (int q = qs + lane; q < qe; q += 32) {
            const int p  = q << 2;
            const int j0 = p - s + i + 1;
            const float4 b0 = sx4[il(j0 + 0)];
            const float4 b1 = sx4[il(j0 + 1)];
            const float4 b2 = sx4[il(j0 + 2)];
            const float4 b3 = sx4[il(j0 + 3)];

            *(float4*)(ob0 + p) = make_float4(a.x*b0.x, a.x*b1.x, a.x*b2.x, a.x*b3.x);
            if (full) {
                *(float4*)(ob1 + p) = make_float4(a.y*b0.y, a.y*b1.y, a.y*b2.y, a.y*b3.y);
                *(float4*)(ob2 + p) = make_float4(a.z*b0.z, a.z*b1.z, a.z*b2.z, a.z*b3.z);
                *(float4*)(ob3 + p) = make_float4(a.w*b0.w, a.w*b1.w, a.w*b2.w, a.w*b3.w);
            } else {
                if (rows_here > 1) *(float4*)(ob1 + p) = make_float4(a.y*b0.y, a.y*b1.y, a.y*b2.y, a.y*b3.y);
                if (rows_here > 2) *(float4*)(ob2 + p) = make_float4(a.z*b0.z, a.z*b1.z, a.z*b2.z, a.z*b3.z);
            }
        }

        // Tail: unaligned end, <=3 elements.
        const int tstart = max(qe << 2, s + head_n);
        const int tail_n = e - tstart;
        if (lane < tail_n) {
            const int p = tstart + lane;
            const int j = p - s + i + 1;
            const float4 b = sx4[il(j)];
            ob0[p] = a.x * b.x;
            if (rows_here > 1) ob1[p] = a.y * b.y;
            if (rows_here > 2) ob2[p] = a.z * b.z;
            if (rows_here > 3) ob3[p] = a.w * b.w;
        }
    }
}

// ---- Generic fallback (idx-driven), used only if npairs != 32640 ----
__global__ __launch_bounds__(256)
void poly_features_generic(const float* __restrict__ x,
                           const int*   __restrict__ idx_a,
                           const int*   __restrict__ idx_b,
                           float*       __restrict__ out,
                           int B, int npairs)
{
    __shared__ float sxl[ROWS_PER_BLOCK][F_FEAT];
    const int row0 = blockIdx.x * ROWS_PER_BLOCK;
    const int tid  = threadIdx.x;
    const size_t out_stride = (size_t)(F_FEAT + npairs);

    #pragma unroll
    for (int r = 0; r < ROWS_PER_BLOCK; r++) {
        int row = row0 + r;
        if (row < B) {
            float v = x[(size_t)row * F_FEAT + tid];
            sxl[r][tid] = v;
            out[(size_t)row * out_stride + tid] = v;
        }
    }
    __syncthreads();

    const int rows_here = min(ROWS_PER_BLOCK, B - row0);
    for (int p = tid; p < npairs; p += 256) {
        int ai = idx_a[p];
        int bi = idx_b[p];
        #pragma unroll
        for (int r = 0; r < ROWS_PER_BLOCK; r++) {
            if (r < rows_here)
                out[(size_t)(row0 + r) * out_stride + F_FEAT + p] = sxl[r][ai] * sxl[r][bi];
        }
    }
}

extern "C" void kernel_launch(void* const* d_in, const int* in_sizes, int n_in,
                              void* d_out, int out_size)
{
    const float* x     = (const float*)d_in[0];
    const int*   idx_a = (const int*)d_in[1];
    const int*   idx_b = (const int*)d_in[2];
    float*       out   = (float*)d_out;

    const int B = in_sizes[0] / F_FEAT;
    const int npairs = in_sizes[1];
    const int grid = (B + ROWS_PER_BLOCK - 1) / ROWS_PER_BLOCK;

    if (npairs == NPAIRS_EXPECTED) {
        poly_features_v10<<<grid, THREADS>>>(x, out, B);
    } else {
        poly_features_generic<<<grid, 256>>>(x, idx_a, idx_b, out, B, npairs);
    }
}

// round 15
// speedup vs baseline: 1.3870x; 1.3870x over previous
#include <cuda_runtime.h>
#include <cstdint>

// PolynomialFeatures: out[b] = concat(x[b], x[b, idx_a] * x[b, idx_b])
// x: [B, 256] fp32, out: [B, 256+32640] fp32.
//
// v11 = v8 skeleton (ROWS=4, p-major grid-stride, analytic combination
// indices with incremental run-boundary tracking, feature-major float4 smem
// so one LDS.128 serves 4 rows, interleaved layout => conflict-free
// j-gather, STG.128 stores), plus:
//  - __launch_bounds__(256, 8): regs==32 exactly -> 8 blocks/SM, 64 warps
//    resident (v8 ran at 7 blocks / occ 71.5%).
//  - no rows_here predication: fast path requires B % 4 == 0 (true here,
//    B=4096); generic fallback otherwise. Fewer regs, branch-free hot loop.
//  - __stcs / divergent quad fast-path from v9 reverted (both regressed).

#define ROWS_PER_BLOCK 4
#define F_FEAT 256
#define THREADS 256
#define NPAIRS_EXPECTED 32640   // 256*255/2
#define NGROUPS 8160            // 32640 / 4

__device__ __forceinline__ int pbase(int i) {
    // start of run i: 255*i - i*(i-1)/2
    return i * 255 - ((i * (i - 1)) >> 1);
}
// interleave: consecutive-by-4 features land in adjacent float4 slots
__device__ __forceinline__ int il(int j) {
    return (j >> 2) + (j & 3) * 64;
}

__global__ __launch_bounds__(THREADS, 8)
void poly_features_v11(const float* __restrict__ x,
                       float*       __restrict__ out)
{
    __shared__ float4 sx4[F_FEAT];   // sx4[il(j)] = {row0..row3} of feature j

    const int row0 = blockIdx.x * ROWS_PER_BLOCK;
    const int t    = threadIdx.x;
    const size_t ostride = (size_t)(F_FEAT + NPAIRS_EXPECTED);

    // Stage feature t for the 4 rows; copy x -> out[:, :F].
    {
        const float v0 = x[(size_t)(row0 + 0) * F_FEAT + t];
        const float v1 = x[(size_t)(row0 + 1) * F_FEAT + t];
        const float v2 = x[(size_t)(row0 + 2) * F_FEAT + t];
        const float v3 = x[(size_t)(row0 + 3) * F_FEAT + t];
        out[(size_t)(row0 + 0) * ostride + t] = v0;
        out[(size_t)(row0 + 1) * ostride + t] = v1;
        out[(size_t)(row0 + 2) * ostride + t] = v2;
        out[(size_t)(row0 + 3) * ostride + t] = v3;
        sx4[il(t)] = make_float4(v0, v1, v2, v3);
    }
    __syncthreads();

    float* ob0 = out + (size_t)(row0 + 0) * ostride + F_FEAT;
    float* ob1 = out + (size_t)(row0 + 1) * ostride + F_FEAT;
    float* ob2 = out + (size_t)(row0 + 2) * ostride + F_FEAT;
    float* ob3 = out + (size_t)(row0 + 3) * ostride + F_FEAT;

    for (int g = t; g < NGROUPS; g += THREADS) {
        const int p = g << 2;

        // Run index guess + exact fixups, carrying run bounds incrementally.
        int i = (int)((511.0f - sqrtf((float)(261121 - 8 * p))) * 0.5f);
        i = max(0, min(i, 254));
        int bi  = pbase(i);          // start of run i
        int bi1 = bi + (255 - i);    // start of run i+1
        while (bi1 <= p) { ++i; bi = bi1; bi1 += 255 - i; }
        while (i > 0 && bi > p) { bi1 = bi; --i; bi -= 255 - i; }

        // Column-streaming: per element, one (a,b) LDS.128 pair feeds one
        // component of each of the 4 output vectors.
        float4 v0, v1, v2, v3;
        {   // e = 0
            const int j = p - bi + i + 1;
            const float4 a = sx4[il(i)];
            const float4 b = sx4[il(j)];
            v0.x = a.x * b.x; v1.x = a.y * b.y; v2.x = a.z * b.z; v3.x = a.w * b.w;
        }
        {   // e = 1
            const int pe = p + 1;
            while (pe >= bi1) { ++i; bi = bi1; bi1 += 255 - i; }
            const int j = pe - bi + i + 1;
            const float4 a = sx4[il(i)];
            const float4 b = sx4[il(j)];
            v0.y = a.x * b.x; v1.y = a.y * b.y; v2.y = a.z * b.z; v3.y = a.w * b.w;
        }
        {   // e = 2
            const int pe = p + 2;
            while (pe >= bi1) { ++i; bi = bi1; bi1 += 255 - i; }
            const int j = pe - bi + i + 1;
            const float4 a = sx4[il(i)];
            const float4 b = sx4[il(j)];
            v0.z = a.x * b.x; v1.z = a.y * b.y; v2.z = a.z * b.z; v3.z = a.w * b.w;
        }
        {   // e = 3
            const int pe = p + 3;
            while (pe >= bi1) { ++i; bi = bi1; bi1 += 255 - i; }
            const int j = pe - bi + i + 1;
            const float4 a = sx4[il(i)];
            const float4 b = sx4[il(j)];
            v0.w = a.x * b.x; v1.w = a.y * b.y; v2.w = a.z * b.z; v3.w = a.w * b.w;
        }

        *(float4*)(ob0 + p) = v0;
        *(float4*)(ob1 + p) = v1;
        *(float4*)(ob2 + p) = v2;
        *(float4*)(ob3 + p) = v3;
    }
}

// ---- Generic fallback (idx-driven), used if shapes don't fit fast path ----
__global__ __launch_bounds__(256)
void poly_features_generic(const float* __restrict__ x,
                           const int*   __restrict__ idx_a,
                           const int*   __restrict__ idx_b,
                           float*       __restrict__ out,
                           int B, int npairs)
{
    __shared__ float sxl[ROWS_PER_BLOCK][F_FEAT];
    const int row0 = blockIdx.x * ROWS_PER_BLOCK;
    const int tid  = threadIdx.x;
    const size_t out_stride = (size_t)(F_FEAT + npairs);

    #pragma unroll
    for (int r = 0; r < ROWS_PER_BLOCK; r++) {
        int row = row0 + r;
        if (row < B) {
            float v = x[(size_t)row * F_FEAT + tid];
            sxl[r][tid] = v;
            out[(size_t)row * out_stride + tid] = v;
        }
    }
    __syncthreads();

    const int rows_here = min(ROWS_PER_BLOCK, B - row0);
    for (int p = tid; p < npairs; p += 256) {
        int ai = idx_a[p];
        int bi = idx_b[p];
        #pragma unroll
        for (int r = 0; r < ROWS_PER_BLOCK; r++) {
            if (r < rows_here)
                out[(size_t)(row0 + r) * out_stride + F_FEAT + p] = sxl[r][ai] * sxl[r][bi];
        }
    }
}

extern "C" void kernel_launch(void* const* d_in, const int* in_sizes, int n_in,
                              void* d_out, int out_size)
{
    const float* x     = (const float*)d_in[0];
    const int*   idx_a = (const int*)d_in[1];
    const int*   idx_b = (const int*)d_in[2];
    float*       out   = (float*)d_out;

    const int B = in_sizes[0] / F_FEAT;
    const int npairs = in_sizes[1];

    if (npairs == NPAIRS_EXPECTED && (B % ROWS_PER_BLOCK) == 0) {
        const int grid = B / ROWS_PER_BLOCK;
        poly_features_v11<<<grid, THREADS>>>(x, out);
    } else {
        const int grid = (B + ROWS_PER_BLOCK - 1) / ROWS_PER_BLOCK;
        poly_features_generic<<<grid, 256>>>(x, idx_a, idx_b, out, B, npairs);
    }
}